// round 5
// baseline (speedup 1.0000x reference)
#include <cuda_runtime.h>

// SeqClassLSTM: B independent LSTM(T=128, in=1, H=32) + FC(32->2).
// FOUR sequences per warp: 128 weight regs (W_hh as packed f32x2) amortized
// over 4 batch elements -> 32 independent 16-deep fma.rn.f32x2 chains per
// step (~256 fma2 burst), amortizing the per-step serial tail (activations,
// c/h update, STS/syncwarp/LDS h-broadcast) that kept issue at 44% in R4.
// Activations via MUFU.TANH. Lane l owns gate rows {l,l+32,l+64,l+96}.

using ull = unsigned long long;

__device__ __forceinline__ ull fma2(ull a, ull b, ull c) {
    ull d;
    asm("fma.rn.f32x2 %0, %1, %2, %3;" : "=l"(d) : "l"(a), "l"(b), "l"(c));
    return d;
}
__device__ __forceinline__ ull pack2(float lo, float hi) {
    ull r;
    asm("mov.b64 %0, {%1, %2};" : "=l"(r) : "f"(lo), "f"(hi));
    return r;
}
__device__ __forceinline__ void unpack2(ull v, float& lo, float& hi) {
    asm("mov.b64 {%0, %1}, %2;" : "=f"(lo), "=f"(hi) : "l"(v));
}
__device__ __forceinline__ float tanh_a(float v) {
    float r;
    asm("tanh.approx.f32 %0, %1;" : "=f"(r) : "f"(v));
    return r;
}
__device__ __forceinline__ float sigmoid_a(float v) {
    return fmaf(0.5f, tanh_a(0.5f * v), 0.5f);
}

constexpr int T = 128;
constexpr int S = 4;     // sequences per warp
constexpr int WPB = 4;   // warps per block

__global__ void __launch_bounds__(128, 2)
lstm_seq_kernel(const float* __restrict__ x,
                const float* __restrict__ W_ih,
                const float* __restrict__ W_hh,
                const float* __restrict__ b_ih,
                const float* __restrict__ b_hh,
                const float* __restrict__ W_fc,
                const float* __restrict__ b_fc,
                float* __restrict__ out,
                int B)
{
    __shared__ __align__(16) float hbuf[2][WPB][S][32];  // [buf][warp][seq][lane]

    const int wblk = threadIdx.x >> 5;
    const int lane = threadIdx.x & 31;
    const int base = (blockIdx.x * WPB + wblk) * S;
    if (base >= B) return;

    // ---- W_hh rows (l, l+32, l+64, l+96) as packed f32x2: 64 ull (128 regs) ----
    const ull* Wr = reinterpret_cast<const ull*>(W_hh);  // row r = Wr + r*16
    ull wi2[16], wf2[16], wg2[16], wo2[16];
#pragma unroll
    for (int j = 0; j < 16; ++j) {
        wi2[j] = Wr[(lane      ) * 16 + j];
        wf2[j] = Wr[(lane + 32 ) * 16 + j];
        wg2[j] = Wr[(lane + 64 ) * 16 + j];
        wo2[j] = Wr[(lane + 96 ) * 16 + j];
    }

    // Pre-packed biases: first fma2 of each chain uses these as c-operand.
    const ull BI = pack2(b_ih[lane      ] + b_hh[lane      ], 0.0f);
    const ull BF = pack2(b_ih[lane + 32 ] + b_hh[lane + 32 ], 0.0f);
    const ull BG = pack2(b_ih[lane + 64 ] + b_hh[lane + 64 ], 0.0f);
    const ull BO = pack2(b_ih[lane + 96 ] + b_hh[lane + 96 ], 0.0f);
    const float wxi = W_ih[lane      ];
    const float wxf = W_ih[lane + 32 ];
    const float wxg = W_ih[lane + 64 ];
    const float wxo = W_ih[lane + 96 ];

    const bool full = (base + S <= B);

    float h[S], c[S];
#pragma unroll
    for (int s = 0; s < S; ++s) { h[s] = 0.0f; c[s] = 0.0f; }

#pragma unroll 1
    for (int tb = 0; tb < 4; ++tb) {
        // Load this 32-step chunk of x for all S sequences (1 float/lane/seq)
        float xv[S];
#pragma unroll
        for (int s = 0; s < S; ++s) {
            const int bs = base + s;
            xv[s] = (full || bs < B) ? x[(size_t)bs * T + tb * 32 + lane] : 0.0f;
        }

#pragma unroll 1
        for (int tt = 0; tt < 32; ++tt) {
            float xt[S];
#pragma unroll
            for (int s = 0; s < S; ++s)
                xt[s] = __shfl_sync(0xffffffffu, xv[s], tt);

#pragma unroll
            for (int s = 0; s < S; ++s)
                hbuf[tt & 1][wblk][s][lane] = h[s];
            __syncwarp();

            ull ai[S], af[S], ag[S], ao[S];
#pragma unroll
            for (int q = 0; q < 8; ++q) {
#pragma unroll
                for (int s = 0; s < S; ++s) {
                    // LDS.128 broadcast: all lanes read same address
                    const ulonglong2 H = reinterpret_cast<const ulonglong2*>(
                        &hbuf[tt & 1][wblk][s][0])[q];
                    if (q == 0) {
                        ai[s] = fma2(wi2[0], H.x, BI);
                        af[s] = fma2(wf2[0], H.x, BF);
                        ag[s] = fma2(wg2[0], H.x, BG);
                        ao[s] = fma2(wo2[0], H.x, BO);
                    } else {
                        ai[s] = fma2(wi2[2*q], H.x, ai[s]);
                        af[s] = fma2(wf2[2*q], H.x, af[s]);
                        ag[s] = fma2(wg2[2*q], H.x, ag[s]);
                        ao[s] = fma2(wo2[2*q], H.x, ao[s]);
                    }
                    ai[s] = fma2(wi2[2*q+1], H.y, ai[s]);
                    af[s] = fma2(wf2[2*q+1], H.y, af[s]);
                    ag[s] = fma2(wg2[2*q+1], H.y, ag[s]);
                    ao[s] = fma2(wo2[2*q+1], H.y, ao[s]);
                }
            }

#pragma unroll
            for (int s = 0; s < S; ++s) {
                float lo, hi;
                unpack2(ai[s], lo, hi); const float gi = fmaf(wxi, xt[s], lo + hi);
                unpack2(af[s], lo, hi); const float gf = fmaf(wxf, xt[s], lo + hi);
                unpack2(ag[s], lo, hi); const float gg = fmaf(wxg, xt[s], lo + hi);
                unpack2(ao[s], lo, hi); const float go = fmaf(wxo, xt[s], lo + hi);

                const float si = sigmoid_a(gi);
                const float sf = sigmoid_a(gf);
                const float tg = tanh_a(gg);
                const float so = sigmoid_a(go);

                c[s] = fmaf(sf, c[s], si * tg);
                h[s] = so * tanh_a(c[s]);
            }
        }
    }

    // ---- FC: out[b, :] = h @ W_fc.T + b_fc  (warp reductions) ----
    const float w0 = W_fc[lane];
    const float w1 = W_fc[32 + lane];
#pragma unroll
    for (int s = 0; s < S; ++s) {
        float v0 = h[s] * w0;
        float v1 = h[s] * w1;
#pragma unroll
        for (int off = 16; off; off >>= 1) {
            v0 += __shfl_xor_sync(0xffffffffu, v0, off);
            v1 += __shfl_xor_sync(0xffffffffu, v1, off);
        }
        const int bs = base + s;
        if (lane == 0 && bs < B) {
            out[(size_t)bs * 2 + 0] = v0 + b_fc[0];
            out[(size_t)bs * 2 + 1] = v1 + b_fc[1];
        }
    }
}

extern "C" void kernel_launch(void* const* d_in, const int* in_sizes, int n_in,
                              void* d_out, int out_size)
{
    const float* x    = (const float*)d_in[0];
    const float* W_ih = (const float*)d_in[1];
    const float* W_hh = (const float*)d_in[2];
    const float* b_ih = (const float*)d_in[3];
    const float* b_hh = (const float*)d_in[4];
    const float* W_fc = (const float*)d_in[5];
    const float* b_fc = (const float*)d_in[6];
    float* out = (float*)d_out;

    const int B = in_sizes[0] / T;                   // x has B*T elements
    const int groups = (B + S - 1) / S;              // S sequences per warp
    const int blocks = (groups + WPB - 1) / WPB;

    lstm_seq_kernel<<<blocks, 128>>>(x, W_ih, W_hh, b_ih, b_hh, W_fc, b_fc, out, B);
}

// round 7
// speedup vs baseline: 2.7277x; 2.7277x over previous
#include <cuda_runtime.h>
#include <cuda_bf16.h>
#include <cstdint>

// SeqClassLSTM via legacy mma.sync bf16 (sm_103-portable; tcgen05 is 'a'-only
// and the harness targets plain sm_103).
// Per warp: 16 seqs. Per step: D[16x128] = A[16 x k] @ B[128 x k]^T with
// m16n8k16 bf16 MMAs, 3-term bf16 split (hi*hi + lo*hi + hi*lo) for fp32-grade
// accuracy, plus one k8 chunk folding bias + W_ih*x_t into the GEMM.
// Gate order n = gate*32+hid: gates i,f,g,o of one (seq,hid) land in ONE
// thread (tiles q,q+4,q+8,q+12) -> thread-local c/h update. h goes back to
// smem via stmatrix (same fragment layout as D), reloaded via ldmatrix.
// Per-warp double-buffered h tile; only __syncwarp per step (no block bars).

using u32 = uint32_t;

constexpr int T = 128;
constexpr int WARPS = 4;
constexpr int SEQ_CTA = 64;

__device__ __forceinline__ u32 sm_addr(const void* p) {
    u32 a;
    asm("{ .reg .u64 t; cvta.to.shared.u64 t, %1; cvt.u32.u64 %0, t; }" : "=r"(a) : "l"(p));
    return a;
}
__device__ __forceinline__ float tanh_a(float v) {
    float r; asm("tanh.approx.f32 %0, %1;" : "=f"(r) : "f"(v)); return r;
}
__device__ __forceinline__ float sigmoid_a(float v) {
    return fmaf(0.5f, tanh_a(0.5f * v), 0.5f);
}
// pack two f32 -> bf16x2; LOW half = first arg
__device__ __forceinline__ u32 packbf(float lo, float hi) {
    __nv_bfloat162 t = __floats2bfloat162_rn(lo, hi);
    return *reinterpret_cast<u32*>(&t);
}

__device__ __forceinline__ void ldm4(u32 r[4], u32 a) {
    asm volatile("ldmatrix.sync.aligned.m8n8.x4.shared.b16 {%0,%1,%2,%3}, [%4];"
                 : "=r"(r[0]), "=r"(r[1]), "=r"(r[2]), "=r"(r[3]) : "r"(a));
}
__device__ __forceinline__ void ldm2(u32 r[2], u32 a) {
    asm volatile("ldmatrix.sync.aligned.m8n8.x2.shared.b16 {%0,%1}, [%2];"
                 : "=r"(r[0]), "=r"(r[1]) : "r"(a));
}
__device__ __forceinline__ void stm4(u32 a, u32 r0, u32 r1, u32 r2, u32 r3) {
    asm volatile("stmatrix.sync.aligned.m8n8.x4.shared.b16 [%0], {%1,%2,%3,%4};"
                 :: "r"(a), "r"(r0), "r"(r1), "r"(r2), "r"(r3) : "memory");
}
__device__ __forceinline__ void lds128(u32 r[4], u32 a) {
    asm volatile("ld.shared.v4.b32 {%0,%1,%2,%3}, [%4];"
                 : "=r"(r[0]), "=r"(r[1]), "=r"(r[2]), "=r"(r[3]) : "r"(a));
}
__device__ __forceinline__ void sts128(u32 a, u32 r0, u32 r1, u32 r2, u32 r3) {
    asm volatile("st.shared.v4.b32 [%0], {%1,%2,%3,%4};"
                 :: "r"(a), "r"(r0), "r"(r1), "r"(r2), "r"(r3) : "memory");
}
__device__ __forceinline__ void mma16816(float d[4], const u32 a[4], u32 b0, u32 b1) {
    asm volatile("mma.sync.aligned.m16n8k16.row.col.f32.bf16.bf16.f32 "
                 "{%0,%1,%2,%3}, {%4,%5,%6,%7}, {%8,%9}, {%0,%1,%2,%3};"
                 : "+f"(d[0]), "+f"(d[1]), "+f"(d[2]), "+f"(d[3])
                 : "r"(a[0]), "r"(a[1]), "r"(a[2]), "r"(a[3]), "r"(b0), "r"(b1));
}
__device__ __forceinline__ void mma1688(float d[4], const u32 a[2], u32 b0) {
    asm volatile("mma.sync.aligned.m16n8k8.row.col.f32.bf16.bf16.f32 "
                 "{%0,%1,%2,%3}, {%4,%5}, {%6}, {%0,%1,%2,%3};"
                 : "+f"(d[0]), "+f"(d[1]), "+f"(d[2]), "+f"(d[3])
                 : "r"(a[0]), "r"(a[1]), "r"(b0));
}

__global__ void __launch_bounds__(128, 3)
lstm_hmma(const float* __restrict__ x,
          const float* __restrict__ W_ih,
          const float* __restrict__ W_hh,
          const float* __restrict__ b_ih,
          const float* __restrict__ b_hh,
          const float* __restrict__ W_fc,
          const float* __restrict__ b_fc,
          float* __restrict__ out,
          int B)
{
    // Btab[(tau*2+g)*32 + lane][4] u32; g=0: W_hi frags (c0 b0,b1, c1 b0,b1),
    // g=1: W_lo frags. 16KB.
    __shared__ u32 Btab[16 * 2 * 32 * 4];
    // Per-warp A buffers: 16 tiles x 128B (hi c0|c1, lo c0|c1), double-buffered.
    __shared__ __align__(16) u32 hbuf[WARPS][2][512];
    __shared__ __align__(16) u32 xtile[WARPS][64];   // [1,1,xhi,xlo,xhi,0,0,0] rows
    __shared__ float wfc_s[64];
    __shared__ float bfc_s[2];

    const int tid = threadIdx.x;
    const int wid = tid >> 5, lane = tid & 31;

    // ---- build weight-fragment table ----
    for (int i = tid; i < 16 * 2 * 32 * 4; i += 128) {
        const int j   = i & 3;
        const int ln  = (i >> 2) & 31;
        const int g   = (i >> 7) & 1;
        const int tau = i >> 8;
        const int n = tau * 8 + (ln >> 2);
        const int k = ((j >> 1) * 16) + ((j & 1) * 8) + 2 * (ln & 3);
        const float w0 = W_hh[n * 32 + k];
        const float w1 = W_hh[n * 32 + k + 1];
        const float h0 = __bfloat162float(__float2bfloat16(w0));
        const float h1 = __bfloat162float(__float2bfloat16(w1));
        Btab[i] = g ? packbf(w0 - h0, w1 - h1) : packbf(w0, w1);
    }

    // ---- per-lane k8 (bias/x) B fragments in registers ----
    u32 bx[16];
    {
        const int sel = lane & 3;
#pragma unroll
        for (int tau = 0; tau < 16; ++tau) {
            const int n = tau * 8 + (lane >> 2);
            const float bias = b_ih[n] + b_hh[n];
            const float wx = W_ih[n];
            const float bh = __bfloat162float(__float2bfloat16(bias));
            const float wh = __bfloat162float(__float2bfloat16(wx));
            u32 v;
            if (sel == 0)      v = packbf(bh, bias - bh);      // k0=b_hi, k1=b_lo
            else if (sel == 1) v = packbf(wh, wh);             // k2,k3 = wx_hi
            else if (sel == 2) v = packbf(wx - wh, 0.0f);      // k4 = wx_lo
            else               v = 0u;
            bx[tau] = v;
        }
    }

    for (int i = tid; i < WARPS * 2 * 512; i += 128) (&hbuf[0][0][0])[i] = 0;
    for (int i = tid; i < WARPS * 64; i += 128) (&xtile[0][0])[i] = 0;
    if (tid < 64) wfc_s[tid] = W_fc[tid];
    if (tid < 2) bfc_s[tid] = b_fc[tid];
    __syncthreads();

    const u32 hb0 = sm_addr(&hbuf[wid][0][0]);
    const u32 hb1 = sm_addr(&hbuf[wid][1][0]);
    const u32 xb  = sm_addr(&xtile[wid][0]);
    const u32 btb = sm_addr(Btab);
    const u32 lmo  = ((u32)(lane >> 3) * 128u) + ((u32)(lane & 7) * 16u);
    const u32 lmo2 = ((u32)((lane >> 3) & 1) * 128u) + ((u32)(lane & 7) * 16u);

    const int seqr = blockIdx.x * SEQ_CTA + wid * 16 + (lane & 15);
    const bool xl = (lane < 16);

    float xn = 0.0f;
    if (xl && seqr < B) xn = __ldg(&x[(size_t)seqr * T]);
    if (xl) {
        const int r = lane & 15;
        const u32 a = xb + ((u32)(r >> 3) * 128u) + ((u32)(r & 7) * 16u);
        const float xh = __bfloat162float(__float2bfloat16(xn));
        sts128(a, 0x3F803F80u, packbf(xh, xn - xh), packbf(xh, 0.0f), 0u);
    }
    __syncwarp();

    float cst[16];
#pragma unroll
    for (int i = 0; i < 16; ++i) cst[i] = 0.0f;

#pragma unroll 1
    for (int t = 0; t < T; ++t) {
        const u32 rb = (t & 1) ? hb1 : hb0;
        const u32 wb = (t & 1) ? hb0 : hb1;
        u32 Ahi0[4], Ahi1[4], Alo0[4], Alo1[4], Ax[2];
        ldm4(Ahi0, rb + lmo);
        ldm4(Ahi1, rb + 512 + lmo);
        ldm4(Alo0, rb + 1024 + lmo);
        ldm4(Alo1, rb + 1536 + lmo);
        ldm2(Ax, xb + lmo2);

        float xnext = 0.0f;
        if (xl && (t + 1) < T && seqr < B) xnext = __ldg(&x[(size_t)seqr * T + t + 1]);

        u32 hst[8], lst[8];
#pragma unroll
        for (int q = 0; q < 4; ++q) {
            float dd[4][4];
#pragma unroll
            for (int gate = 0; gate < 4; ++gate) {
                const int tau = q + gate * 4;
                float* d = dd[gate];
                d[0] = 0.0f; d[1] = 0.0f; d[2] = 0.0f; d[3] = 0.0f;
                u32 bh[4], bl[4];
                lds128(bh, btb + (u32)(tau * 64 + lane) * 16u);
                lds128(bl, btb + (u32)(tau * 64 + 32 + lane) * 16u);
                mma16816(d, Ahi0, bh[0], bh[1]);
                mma16816(d, Ahi1, bh[2], bh[3]);
                mma16816(d, Alo0, bh[0], bh[1]);
                mma16816(d, Alo1, bh[2], bh[3]);
                mma16816(d, Ahi0, bl[0], bl[1]);
                mma16816(d, Ahi1, bl[2], bl[3]);
                mma1688(d, Ax, bx[tau]);
            }
            float hv[4];
#pragma unroll
            for (int e = 0; e < 4; ++e) {
                const float si = sigmoid_a(dd[0][e]);
                const float sf = sigmoid_a(dd[1][e]);
                const float tg = tanh_a(dd[2][e]);
                const float so = sigmoid_a(dd[3][e]);
                const float cn = fmaf(sf, cst[q * 4 + e], si * tg);
                cst[q * 4 + e] = cn;
                hv[e] = so * tanh_a(cn);
            }
            const u32 p0 = packbf(hv[0], hv[1]);        // (rg0: cols 2a,2a+1)
            const u32 p1 = packbf(hv[2], hv[3]);        // (rg1)
            const float r00 = __uint_as_float(p0 << 16);
            const float r01 = __uint_as_float(p0 & 0xFFFF0000u);
            const float r10 = __uint_as_float(p1 << 16);
            const float r11 = __uint_as_float(p1 & 0xFFFF0000u);
            hst[q * 2 + 0] = p0;
            hst[q * 2 + 1] = p1;
            lst[q * 2 + 0] = packbf(hv[0] - r00, hv[1] - r01);
            lst[q * 2 + 1] = packbf(hv[2] - r10, hv[3] - r11);
        }
        stm4(wb + lmo,        hst[0], hst[1], hst[2], hst[3]);
        stm4(wb + 512 + lmo,  hst[4], hst[5], hst[6], hst[7]);
        stm4(wb + 1024 + lmo, lst[0], lst[1], lst[2], lst[3]);
        stm4(wb + 1536 + lmo, lst[4], lst[5], lst[6], lst[7]);
        if (xl) {
            const int r = lane & 15;
            const u32 a = xb + ((u32)(r >> 3) * 128u) + ((u32)(r & 7) * 16u);
            const float xh = __bfloat162float(__float2bfloat16(xnext));
            sts128(a, 0x3F803F80u, packbf(xh, xnext - xh), packbf(xh, 0.0f), 0u);
        }
        __syncwarp();
    }

    // ---- FC from final h (in hbuf par 0; T even) ----
    float acc[2][2] = {{0.0f, 0.0f}, {0.0f, 0.0f}};
    const int a2 = 2 * (lane & 3);
    const int r0 = lane >> 2;
#pragma unroll
    for (int q = 0; q < 4; ++q) {
#pragma unroll
        for (int e = 0; e < 2; ++e) {
            const int hid = 8 * q + a2 + e;
            const int chunk = hid >> 4;
            const int kk = hid & 15;
            const int khalf = kk >> 3;
            const int col = kk & 7;
            const float f0 = wfc_s[hid];
            const float f1 = wfc_s[32 + hid];
#pragma unroll
            for (int rg = 0; rg < 2; ++rg) {
                const u32 ahi = hb0 + (u32)(chunk * 4 + khalf * 2 + rg) * 128u
                              + (u32)r0 * 16u + (u32)col * 2u;
                u32 hv16, lv16;
                asm volatile("ld.shared.u16 %0, [%1];" : "=r"(hv16) : "r"(ahi));
                asm volatile("ld.shared.u16 %0, [%1];" : "=r"(lv16) : "r"(ahi + 1024u));
                const float h = __uint_as_float(hv16 << 16) + __uint_as_float(lv16 << 16);
                acc[rg][0] = fmaf(h, f0, acc[rg][0]);
                acc[rg][1] = fmaf(h, f1, acc[rg][1]);
            }
        }
    }
#pragma unroll
    for (int rg = 0; rg < 2; ++rg)
#pragma unroll
        for (int o = 0; o < 2; ++o) {
            acc[rg][o] += __shfl_xor_sync(0xffffffffu, acc[rg][o], 1);
            acc[rg][o] += __shfl_xor_sync(0xffffffffu, acc[rg][o], 2);
        }
    if ((lane & 3) == 0) {
        const int s0 = blockIdx.x * SEQ_CTA + wid * 16 + r0;
        if (s0 < B) {
            out[(size_t)s0 * 2 + 0] = acc[0][0] + bfc_s[0];
            out[(size_t)s0 * 2 + 1] = acc[0][1] + bfc_s[1];
        }
        const int s1 = s0 + 8;
        if (s1 < B) {
            out[(size_t)s1 * 2 + 0] = acc[1][0] + bfc_s[0];
            out[(size_t)s1 * 2 + 1] = acc[1][1] + bfc_s[1];
        }
    }
}

extern "C" void kernel_launch(void* const* d_in, const int* in_sizes, int n_in,
                              void* d_out, int out_size)
{
    const float* x    = (const float*)d_in[0];
    const float* W_ih = (const float*)d_in[1];
    const float* W_hh = (const float*)d_in[2];
    const float* b_ih = (const float*)d_in[3];
    const float* b_hh = (const float*)d_in[4];
    const float* W_fc = (const float*)d_in[5];
    const float* b_fc = (const float*)d_in[6];
    float* out = (float*)d_out;

    const int B = in_sizes[0] / T;                // x has B*T elements
    const int blocks = (B + SEQ_CTA - 1) / SEQ_CTA;

    lstm_hmma<<<blocks, 128>>>(x, W_ih, W_hh, b_ih, b_hh, W_fc, b_fc, out, B);
}

// round 8
// speedup vs baseline: 3.5248x; 1.2922x over previous
#include <cuda_runtime.h>
#include <cuda_fp16.h>
#include <cstdint>

// SeqClassLSTM via legacy mma.sync fp16 (sm_103-portable).
// R8: fp16 2-term split replaces bf16 3-term. h is bounded (-1,1) so a single
// fp16 h carries abs err <= 2^-12 (no h split); W_hh kept as fp16 hi+lo pair;
// fp16 x fp16 products are exact in fp32 accumulation. 5 MMAs/tile (was 7):
//   h*W_hi (2x k16) + h*W_lo (2x k16) + k8 (bias/x, fp16-split).
// Per warp: 16 seqs. Gate order n = gate*32+hid: gates i,f,g,o of one
// (seq,hid) land in ONE thread (tiles q,q+4,q+8,q+12) -> thread-local c/h
// update. h -> smem via stmatrix (D-frag layout), back via ldmatrix.
// Per-warp double-buffered h tile; only __syncwarp per step.

using u32 = uint32_t;

constexpr int T = 128;
constexpr int WARPS = 4;
constexpr int SEQ_CTA = 64;

__device__ __forceinline__ u32 sm_addr(const void* p) {
    u32 a;
    asm("{ .reg .u64 t; cvta.to.shared.u64 t, %1; cvt.u32.u64 %0, t; }" : "=r"(a) : "l"(p));
    return a;
}
__device__ __forceinline__ float tanh_a(float v) {
    float r; asm("tanh.approx.f32 %0, %1;" : "=f"(r) : "f"(v)); return r;
}
__device__ __forceinline__ float sigmoid_a(float v) {
    return fmaf(0.5f, tanh_a(0.5f * v), 0.5f);
}
// pack two f32 -> half2; LOW half = first arg
__device__ __forceinline__ u32 packh(float lo, float hi) {
    __half2 t = __floats2half2_rn(lo, hi);
    return *reinterpret_cast<u32*>(&t);
}

__device__ __forceinline__ void ldm4(u32 r[4], u32 a) {
    asm volatile("ldmatrix.sync.aligned.m8n8.x4.shared.b16 {%0,%1,%2,%3}, [%4];"
                 : "=r"(r[0]), "=r"(r[1]), "=r"(r[2]), "=r"(r[3]) : "r"(a));
}
__device__ __forceinline__ void ldm2(u32 r[2], u32 a) {
    asm volatile("ldmatrix.sync.aligned.m8n8.x2.shared.b16 {%0,%1}, [%2];"
                 : "=r"(r[0]), "=r"(r[1]) : "r"(a));
}
__device__ __forceinline__ void stm4(u32 a, u32 r0, u32 r1, u32 r2, u32 r3) {
    asm volatile("stmatrix.sync.aligned.m8n8.x4.shared.b16 [%0], {%1,%2,%3,%4};"
                 :: "r"(a), "r"(r0), "r"(r1), "r"(r2), "r"(r3) : "memory");
}
__device__ __forceinline__ void lds128(u32 r[4], u32 a) {
    asm volatile("ld.shared.v4.b32 {%0,%1,%2,%3}, [%4];"
                 : "=r"(r[0]), "=r"(r[1]), "=r"(r[2]), "=r"(r[3]) : "r"(a));
}
__device__ __forceinline__ void sts128(u32 a, u32 r0, u32 r1, u32 r2, u32 r3) {
    asm volatile("st.shared.v4.b32 [%0], {%1,%2,%3,%4};"
                 :: "r"(a), "r"(r0), "r"(r1), "r"(r2), "r"(r3) : "memory");
}
__device__ __forceinline__ void mma16816(float d[4], const u32 a[4], u32 b0, u32 b1) {
    asm volatile("mma.sync.aligned.m16n8k16.row.col.f32.f16.f16.f32 "
                 "{%0,%1,%2,%3}, {%4,%5,%6,%7}, {%8,%9}, {%0,%1,%2,%3};"
                 : "+f"(d[0]), "+f"(d[1]), "+f"(d[2]), "+f"(d[3])
                 : "r"(a[0]), "r"(a[1]), "r"(a[2]), "r"(a[3]), "r"(b0), "r"(b1));
}
__device__ __forceinline__ void mma1688(float d[4], const u32 a[2], u32 b0) {
    asm volatile("mma.sync.aligned.m16n8k8.row.col.f32.f16.f16.f32 "
                 "{%0,%1,%2,%3}, {%4,%5}, {%6}, {%0,%1,%2,%3};"
                 : "+f"(d[0]), "+f"(d[1]), "+f"(d[2]), "+f"(d[3])
                 : "r"(a[0]), "r"(a[1]), "r"(b0));
}

__global__ void __launch_bounds__(128, 3)
lstm_hmma(const float* __restrict__ x,
          const float* __restrict__ W_ih,
          const float* __restrict__ W_hh,
          const float* __restrict__ b_ih,
          const float* __restrict__ b_hh,
          const float* __restrict__ W_fc,
          const float* __restrict__ b_fc,
          float* __restrict__ out,
          int B)
{
    // Btab[(tau*2+g)*32 + lane][4] u32; g=0: W_hi frags, g=1: W_lo frags. 16KB.
    __shared__ u32 Btab[16 * 2 * 32 * 4];
    // Per-warp A buffers: 16x32 fp16 = 1KB each, double-buffered.
    __shared__ __align__(16) u32 hbuf[WARPS][2][256];
    __shared__ __align__(16) u32 xtile[WARPS][64];   // [1,1,xhi,xlo,xhi,0,0,0] rows
    __shared__ float wfc_s[64];
    __shared__ float bfc_s[2];

    const int tid = threadIdx.x;
    const int wid = tid >> 5, lane = tid & 31;

    // ---- build weight-fragment table (fp16 hi/lo split of W_hh) ----
    for (int i = tid; i < 16 * 2 * 32 * 4; i += 128) {
        const int j   = i & 3;
        const int ln  = (i >> 2) & 31;
        const int g   = (i >> 7) & 1;
        const int tau = i >> 8;
        const int n = tau * 8 + (ln >> 2);
        const int k = ((j >> 1) * 16) + ((j & 1) * 8) + 2 * (ln & 3);
        const float w0 = W_hh[n * 32 + k];
        const float w1 = W_hh[n * 32 + k + 1];
        const float h0 = __half2float(__float2half_rn(w0));
        const float h1 = __half2float(__float2half_rn(w1));
        Btab[i] = g ? packh(w0 - h0, w1 - h1) : packh(w0, w1);
    }

    // ---- per-lane k8 (bias/x) B fragments in registers (fp16) ----
    u32 bx[16];
    {
        const int sel = lane & 3;
#pragma unroll
        for (int tau = 0; tau < 16; ++tau) {
            const int n = tau * 8 + (lane >> 2);
            const float bias = b_ih[n] + b_hh[n];
            const float wx = W_ih[n];
            const float bh = __half2float(__float2half_rn(bias));
            const float wh = __half2float(__float2half_rn(wx));
            u32 v;
            if (sel == 0)      v = packh(bh, bias - bh);      // k0=b_hi, k1=b_lo
            else if (sel == 1) v = packh(wh, wh);             // k2,k3 = wx_hi
            else if (sel == 2) v = packh(wx - wh, 0.0f);      // k4 = wx_lo
            else               v = 0u;
            bx[tau] = v;
        }
    }

    for (int i = tid; i < WARPS * 2 * 256; i += 128) (&hbuf[0][0][0])[i] = 0;
    for (int i = tid; i < WARPS * 64; i += 128) (&xtile[0][0])[i] = 0;
    if (tid < 64) wfc_s[tid] = W_fc[tid];
    if (tid < 2) bfc_s[tid] = b_fc[tid];
    __syncthreads();

    const u32 hb0 = sm_addr(&hbuf[wid][0][0]);
    const u32 hb1 = sm_addr(&hbuf[wid][1][0]);
    const u32 xb  = sm_addr(&xtile[wid][0]);
    const u32 btb = sm_addr(Btab);
    const u32 lmo  = ((u32)(lane >> 3) * 128u) + ((u32)(lane & 7) * 16u);
    const u32 lmo2 = ((u32)((lane >> 3) & 1) * 128u) + ((u32)(lane & 7) * 16u);

    const int seqr = blockIdx.x * SEQ_CTA + wid * 16 + (lane & 15);
    const bool xl = (lane < 16);

    float xn = 0.0f;
    if (xl && seqr < B) xn = __ldg(&x[(size_t)seqr * T]);
    if (xl) {
        const int r = lane & 15;
        const u32 a = xb + ((u32)(r >> 3) * 128u) + ((u32)(r & 7) * 16u);
        const float xh = __half2float(__float2half_rn(xn));
        sts128(a, 0x3C003C00u, packh(xh, xn - xh), packh(xh, 0.0f), 0u);
    }
    __syncwarp();

    float cst[16];
#pragma unroll
    for (int i = 0; i < 16; ++i) cst[i] = 0.0f;

#pragma unroll 1
    for (int t = 0; t < T; ++t) {
        const u32 rb = (t & 1) ? hb1 : hb0;
        const u32 wb = (t & 1) ? hb0 : hb1;
        u32 Ahi0[4], Ahi1[4], Ax[2];
        ldm4(Ahi0, rb + lmo);
        ldm4(Ahi1, rb + 512 + lmo);
        ldm2(Ax, xb + lmo2);

        float xnext = 0.0f;
        if (xl && (t + 1) < T && seqr < B) xnext = __ldg(&x[(size_t)seqr * T + t + 1]);

        u32 hst[8];
#pragma unroll
        for (int q = 0; q < 4; ++q) {
            float dd[4][4];
#pragma unroll
            for (int gate = 0; gate < 4; ++gate) {
                const int tau = q + gate * 4;
                float* d = dd[gate];
                d[0] = 0.0f; d[1] = 0.0f; d[2] = 0.0f; d[3] = 0.0f;
                u32 bh[4], bl[4];
                lds128(bh, btb + (u32)(tau * 64 + lane) * 16u);
                lds128(bl, btb + (u32)(tau * 64 + 32 + lane) * 16u);
                mma16816(d, Ahi0, bh[0], bh[1]);
                mma16816(d, Ahi1, bh[2], bh[3]);
                mma16816(d, Ahi0, bl[0], bl[1]);
                mma16816(d, Ahi1, bl[2], bl[3]);
                mma1688(d, Ax, bx[tau]);
            }
            float hv[4];
#pragma unroll
            for (int e = 0; e < 4; ++e) {
                const float si = sigmoid_a(dd[0][e]);
                const float sf = sigmoid_a(dd[1][e]);
                const float tg = tanh_a(dd[2][e]);
                const float so = sigmoid_a(dd[3][e]);
                const float cn = fmaf(sf, cst[q * 4 + e], si * tg);
                cst[q * 4 + e] = cn;
                hv[e] = so * tanh_a(cn);
            }
            hst[q * 2 + 0] = packh(hv[0], hv[1]);   // cols 2a,2a+1; rows r0
            hst[q * 2 + 1] = packh(hv[2], hv[3]);   // rows r0+8
        }
        stm4(wb + lmo,       hst[0], hst[1], hst[2], hst[3]);
        stm4(wb + 512 + lmo, hst[4], hst[5], hst[6], hst[7]);
        if (xl) {
            const int r = lane & 15;
            const u32 a = xb + ((u32)(r >> 3) * 128u) + ((u32)(r & 7) * 16u);
            const float xh = __half2float(__float2half_rn(xnext));
            sts128(a, 0x3C003C00u, packh(xh, xnext - xh), packh(xh, 0.0f), 0u);
        }
        __syncwarp();
    }

    // ---- FC from final h (in hbuf par 0; T even) ----
    float acc[2][2] = {{0.0f, 0.0f}, {0.0f, 0.0f}};
    const int a2 = 2 * (lane & 3);
    const int r0 = lane >> 2;
#pragma unroll
    for (int q = 0; q < 4; ++q) {
#pragma unroll
        for (int e = 0; e < 2; ++e) {
            const int hid = 8 * q + a2 + e;
            const int chunk = hid >> 4;
            const int kk = hid & 15;
            const int khalf = kk >> 3;
            const int col = kk & 7;
            const float f0 = wfc_s[hid];
            const float f1 = wfc_s[32 + hid];
#pragma unroll
            for (int rg = 0; rg < 2; ++rg) {
                const u32 ahi = hb0 + (u32)(chunk * 4 + khalf * 2 + rg) * 128u
                              + (u32)r0 * 16u + (u32)col * 2u;
                u32 hv16;
                asm volatile("ld.shared.u16 %0, [%1];" : "=r"(hv16) : "r"(ahi));
                __half hh = *reinterpret_cast<__half*>(&hv16);
                const float h = __half2float(hh);
                acc[rg][0] = fmaf(h, f0, acc[rg][0]);
                acc[rg][1] = fmaf(h, f1, acc[rg][1]);
            }
        }
    }
#pragma unroll
    for (int rg = 0; rg < 2; ++rg)
#pragma unroll
        for (int o = 0; o < 2; ++o) {
            acc[rg][o] += __shfl_xor_sync(0xffffffffu, acc[rg][o], 1);
            acc[rg][o] += __shfl_xor_sync(0xffffffffu, acc[rg][o], 2);
        }
    if ((lane & 3) == 0) {
        const int s0 = blockIdx.x * SEQ_CTA + wid * 16 + r0;
        if (s0 < B) {
            out[(size_t)s0 * 2 + 0] = acc[0][0] + bfc_s[0];
            out[(size_t)s0 * 2 + 1] = acc[0][1] + bfc_s[1];
        }
        const int s1 = s0 + 8;
        if (s1 < B) {
            out[(size_t)s1 * 2 + 0] = acc[1][0] + bfc_s[0];
            out[(size_t)s1 * 2 + 1] = acc[1][1] + bfc_s[1];
        }
    }
}

extern "C" void kernel_launch(void* const* d_in, const int* in_sizes, int n_in,
                              void* d_out, int out_size)
{
    const float* x    = (const float*)d_in[0];
    const float* W_ih = (const float*)d_in[1];
    const float* W_hh = (const float*)d_in[2];
    const float* b_ih = (const float*)d_in[3];
    const float* b_hh = (const float*)d_in[4];
    const float* W_fc = (const float*)d_in[5];
    const float* b_fc = (const float*)d_in[6];
    float* out = (float*)d_out;

    const int B = in_sizes[0] / T;                // x has B*T elements
    const int blocks = (B + SEQ_CTA - 1) / SEQ_CTA;

    lstm_hmma<<<blocks, 128>>>(x, W_ih, W_hh, b_ih, b_hh, W_fc, b_fc, out, B);
}

// round 9
// speedup vs baseline: 3.6029x; 1.0221x over previous
#include <cuda_runtime.h>
#include <cuda_fp16.h>
#include <cstdint>

// SeqClassLSTM via mma.sync fp16 (sm_103-portable).
// R9: (1) activations via tanh.approx.f16x2 — one MUFU per TWO activations
// (MUFU was a ~600us chip floor at f32); c update stays fp32.
// (2) 32 seqs/warp as two 16-row blocks sharing every B-fragment LDS.128 —
// halves Btab L1 traffic per sequence (L1 was 66%).
// Per rb-block the tile machinery is identical to the proven R8 kernel:
// gate order n=gate*32+hid puts gates i,f,g,o of a (seq,hid) in ONE thread;
// h -> smem via stmatrix (D-frag layout), back via ldmatrix; per-warp double
// buffer; only __syncwarp per step.

using u32 = uint32_t;

constexpr int T = 128;
constexpr int WARPS = 4;
constexpr int SEQ_CTA = 128;   // 32 per warp

__device__ __forceinline__ u32 sm_addr(const void* p) {
    u32 a;
    asm("{ .reg .u64 t; cvta.to.shared.u64 t, %1; cvt.u32.u64 %0, t; }" : "=r"(a) : "l"(p));
    return a;
}
// pack two f32 -> half2 (u32); LOW half = first arg
__device__ __forceinline__ u32 packh(float lo, float hi) {
    __half2 t = __floats2half2_rn(lo, hi);
    return *reinterpret_cast<u32*>(&t);
}
__device__ __forceinline__ __half2 asH2(u32 v) { return *reinterpret_cast<__half2*>(&v); }
__device__ __forceinline__ u32 asU(__half2 v) { return *reinterpret_cast<u32*>(&v); }
__device__ __forceinline__ __half2 tanh_h2(__half2 v) {
    u32 r, a = asU(v);
    asm("tanh.approx.f16x2 %0, %1;" : "=r"(r) : "r"(a));
    return asH2(r);
}

__device__ __forceinline__ void ldm4(u32 r[4], u32 a) {
    asm volatile("ldmatrix.sync.aligned.m8n8.x4.shared.b16 {%0,%1,%2,%3}, [%4];"
                 : "=r"(r[0]), "=r"(r[1]), "=r"(r[2]), "=r"(r[3]) : "r"(a));
}
__device__ __forceinline__ void ldm2(u32 r[2], u32 a) {
    asm volatile("ldmatrix.sync.aligned.m8n8.x2.shared.b16 {%0,%1}, [%2];"
                 : "=r"(r[0]), "=r"(r[1]) : "r"(a));
}
__device__ __forceinline__ void stm4(u32 a, u32 r0, u32 r1, u32 r2, u32 r3) {
    asm volatile("stmatrix.sync.aligned.m8n8.x4.shared.b16 [%0], {%1,%2,%3,%4};"
                 :: "r"(a), "r"(r0), "r"(r1), "r"(r2), "r"(r3) : "memory");
}
__device__ __forceinline__ void lds128(u32 r[4], u32 a) {
    asm volatile("ld.shared.v4.b32 {%0,%1,%2,%3}, [%4];"
                 : "=r"(r[0]), "=r"(r[1]), "=r"(r[2]), "=r"(r[3]) : "r"(a));
}
__device__ __forceinline__ u32 lds32(u32 a) {
    u32 r;
    asm volatile("ld.shared.u32 %0, [%1];" : "=r"(r) : "r"(a));
    return r;
}
__device__ __forceinline__ void sts128(u32 a, u32 r0, u32 r1, u32 r2, u32 r3) {
    asm volatile("st.shared.v4.b32 [%0], {%1,%2,%3,%4};"
                 :: "r"(a), "r"(r0), "r"(r1), "r"(r2), "r"(r3) : "memory");
}
__device__ __forceinline__ void mma16816(float d[4], const u32 a[4], u32 b0, u32 b1) {
    asm volatile("mma.sync.aligned.m16n8k16.row.col.f32.f16.f16.f32 "
                 "{%0,%1,%2,%3}, {%4,%5,%6,%7}, {%8,%9}, {%0,%1,%2,%3};"
                 : "+f"(d[0]), "+f"(d[1]), "+f"(d[2]), "+f"(d[3])
                 : "r"(a[0]), "r"(a[1]), "r"(a[2]), "r"(a[3]), "r"(b0), "r"(b1));
}
__device__ __forceinline__ void mma1688(float d[4], const u32 a[2], u32 b0) {
    asm volatile("mma.sync.aligned.m16n8k8.row.col.f32.f16.f16.f32 "
                 "{%0,%1,%2,%3}, {%4,%5}, {%6}, {%0,%1,%2,%3};"
                 : "+f"(d[0]), "+f"(d[1]), "+f"(d[2]), "+f"(d[3])
                 : "r"(a[0]), "r"(a[1]), "r"(b0));
}

__global__ void __launch_bounds__(128, 3)
lstm_hmma(const float* __restrict__ x,
          const float* __restrict__ W_ih,
          const float* __restrict__ W_hh,
          const float* __restrict__ b_ih,
          const float* __restrict__ b_hh,
          const float* __restrict__ W_fc,
          const float* __restrict__ b_fc,
          float* __restrict__ out,
          int B)
{
    // Btab[(tau*2+g)*32 + lane][4]; g=0: W_hi frags, g=1: W_lo frags. 16KB.
    __shared__ u32 Btab[16 * 2 * 32 * 4];
    __shared__ u32 bxs[16 * 32];                       // k8 bias/x B-frags, 2KB
    // Per-warp A buffers: 2 rb-blocks x 1KB, double-buffered. 16KB.
    __shared__ __align__(16) u32 hbuf[WARPS][2][512];
    __shared__ __align__(16) u32 xtile[WARPS][128];    // 32 rows x 16B
    __shared__ float wfc_s[64];
    __shared__ float bfc_s[2];

    const int tid = threadIdx.x;
    const int wid = tid >> 5, lane = tid & 31;

    // ---- weight-fragment table (fp16 hi/lo split of W_hh) ----
    for (int i = tid; i < 16 * 2 * 32 * 4; i += 128) {
        const int j   = i & 3;
        const int ln  = (i >> 2) & 31;
        const int g   = (i >> 7) & 1;
        const int tau = i >> 8;
        const int n = tau * 8 + (ln >> 2);
        const int k = ((j >> 1) * 16) + ((j & 1) * 8) + 2 * (ln & 3);
        const float w0 = W_hh[n * 32 + k];
        const float w1 = W_hh[n * 32 + k + 1];
        const float h0 = __half2float(__float2half_rn(w0));
        const float h1 = __half2float(__float2half_rn(w1));
        Btab[i] = g ? packh(w0 - h0, w1 - h1) : packh(w0, w1);
    }
    // ---- k8 (bias/x) B fragments table ----
    for (int i = tid; i < 16 * 32; i += 128) {
        const int ln = i & 31, tau = i >> 5;
        const int sel = ln & 3;
        const int n = tau * 8 + (ln >> 2);
        const float bias = b_ih[n] + b_hh[n];
        const float wx = W_ih[n];
        const float bh = __half2float(__float2half_rn(bias));
        const float wh = __half2float(__float2half_rn(wx));
        u32 v;
        if (sel == 0)      v = packh(bh, bias - bh);      // k0=b_hi, k1=b_lo
        else if (sel == 1) v = packh(wh, wh);             // k2,k3 = wx_hi
        else if (sel == 2) v = packh(wx - wh, 0.0f);      // k4 = wx_lo
        else               v = 0u;
        bxs[i] = v;
    }

    for (int i = tid; i < WARPS * 2 * 512; i += 128) (&hbuf[0][0][0])[i] = 0;
    for (int i = tid; i < WARPS * 128; i += 128) (&xtile[0][0])[i] = 0;
    if (tid < 64) wfc_s[tid] = W_fc[tid];
    if (tid < 2) bfc_s[tid] = b_fc[tid];
    __syncthreads();

    const u32 hb0 = sm_addr(&hbuf[wid][0][0]);
    const u32 hb1 = sm_addr(&hbuf[wid][1][0]);
    const u32 xb  = sm_addr(&xtile[wid][0]);
    const u32 btb = sm_addr(Btab);
    const u32 bxb = sm_addr(bxs);
    const u32 lmo  = ((u32)(lane >> 3) * 128u) + ((u32)(lane & 7) * 16u);
    const u32 lmo2 = ((u32)((lane >> 3) & 1) * 128u) + ((u32)(lane & 7) * 16u);

    // each lane owns x-row = lane (seq within warp)
    const int seqr = blockIdx.x * SEQ_CTA + wid * 32 + lane;
    const bool sv = (seqr < B);

    float xn = sv ? __ldg(&x[(size_t)seqr * T]) : 0.0f;
    {
        const float xh = __half2float(__float2half_rn(xn));
        sts128(xb + (u32)lane * 16u, 0x3C003C00u, packh(xh, xn - xh), packh(xh, 0.0f), 0u);
    }
    __syncwarp();

    float cst[32];
#pragma unroll
    for (int i = 0; i < 32; ++i) cst[i] = 0.0f;

    const __half2 H05 = __floats2half2_rn(0.5f, 0.5f);

#pragma unroll 1
    for (int t = 0; t < T; ++t) {
        const u32 rbuf = (t & 1) ? hb1 : hb0;
        const u32 wbuf = (t & 1) ? hb0 : hb1;
        u32 A0[2][4], A1[2][4], Ax[2][2];
#pragma unroll
        for (int rb = 0; rb < 2; ++rb) {
            ldm4(A0[rb], rbuf + (u32)rb * 1024u + lmo);
            ldm4(A1[rb], rbuf + (u32)rb * 1024u + 512u + lmo);
            ldm2(Ax[rb], xb + (u32)rb * 256u + lmo2);
        }

        float xnext = (sv && (t + 1) < T) ? __ldg(&x[(size_t)seqr * T + t + 1]) : 0.0f;

        u32 hst[2][8];
#pragma unroll
        for (int q = 0; q < 4; ++q) {
            float dd[2][4][4];
#pragma unroll
            for (int gate = 0; gate < 4; ++gate) {
                const int tau = q + gate * 4;
                u32 bh[4], bl[4];
                lds128(bh, btb + (u32)(tau * 64 + lane) * 16u);
                lds128(bl, btb + (u32)(tau * 64 + 32 + lane) * 16u);
                const u32 bxv = lds32(bxb + (u32)(tau * 32 + lane) * 4u);
#pragma unroll
                for (int rb = 0; rb < 2; ++rb) {
                    float* d = dd[rb][gate];
                    d[0] = 0.0f; d[1] = 0.0f; d[2] = 0.0f; d[3] = 0.0f;
                    mma16816(d, A0[rb], bh[0], bh[1]);
                    mma16816(d, A1[rb], bh[2], bh[3]);
                    mma16816(d, A0[rb], bl[0], bl[1]);
                    mma16816(d, A1[rb], bl[2], bl[3]);
                    mma1688(d, Ax[rb], bxv);
                }
            }
            // f16x2 epilogue: 10 MUFU per (q,rb) covering 4 cells
#pragma unroll
            for (int rb = 0; rb < 2; ++rb) {
#pragma unroll
                for (int pr = 0; pr < 2; ++pr) {
                    const int e = 2 * pr;
                    const __half2 iv = asH2(packh(dd[rb][0][e], dd[rb][0][e + 1]));
                    const __half2 fv = asH2(packh(dd[rb][1][e], dd[rb][1][e + 1]));
                    const __half2 gv = asH2(packh(dd[rb][2][e], dd[rb][2][e + 1]));
                    const __half2 ov = asH2(packh(dd[rb][3][e], dd[rb][3][e + 1]));
                    const __half2 si = __hfma2(tanh_h2(__hmul2(iv, H05)), H05, H05);
                    const __half2 sf = __hfma2(tanh_h2(__hmul2(fv, H05)), H05, H05);
                    const __half2 tg = tanh_h2(gv);
                    const __half2 so = __hfma2(tanh_h2(__hmul2(ov, H05)), H05, H05);
                    const __half2 p = __hmul2(si, tg);
                    const int ci = (rb * 2 + pr) * 8 + q * 2;
                    const float cn0 = fmaf(__low2float(sf),  cst[ci],     __low2float(p));
                    const float cn1 = fmaf(__high2float(sf), cst[ci + 1], __high2float(p));
                    cst[ci] = cn0;
                    cst[ci + 1] = cn1;
                    const __half2 tc = tanh_h2(asH2(packh(cn0, cn1)));
                    hst[rb][q * 2 + pr] = asU(__hmul2(so, tc));
                }
            }
        }
#pragma unroll
        for (int rb = 0; rb < 2; ++rb) {
            stm4(wbuf + (u32)rb * 1024u + lmo,
                 hst[rb][0], hst[rb][1], hst[rb][2], hst[rb][3]);
            stm4(wbuf + (u32)rb * 1024u + 512u + lmo,
                 hst[rb][4], hst[rb][5], hst[rb][6], hst[rb][7]);
        }
        {
            const float xh = __half2float(__float2half_rn(xnext));
            sts128(xb + (u32)lane * 16u, 0x3C003C00u, packh(xh, xnext - xh),
                   packh(xh, 0.0f), 0u);
        }
        __syncwarp();
    }

    // ---- FC from final h (hbuf parity 0; T even) ----
    const int a2 = 2 * (lane & 3);
    const int r0 = lane >> 2;
#pragma unroll
    for (int rb = 0; rb < 2; ++rb) {
        float acc[2][2] = {{0.0f, 0.0f}, {0.0f, 0.0f}};
#pragma unroll
        for (int q = 0; q < 4; ++q) {
#pragma unroll
            for (int e = 0; e < 2; ++e) {
                const int hid = 8 * q + a2 + e;
                const int chunk = hid >> 4;
                const int kk = hid & 15;
                const int khalf = kk >> 3;
                const int col = kk & 7;
                const float f0 = wfc_s[hid];
                const float f1 = wfc_s[32 + hid];
#pragma unroll
                for (int rg = 0; rg < 2; ++rg) {
                    const u32 ahi = hb0 + (u32)rb * 1024u
                                  + (u32)(chunk * 4 + khalf * 2 + rg) * 128u
                                  + (u32)r0 * 16u + (u32)col * 2u;
                    u32 hv16;
                    asm volatile("ld.shared.u16 %0, [%1];" : "=r"(hv16) : "r"(ahi));
                    const float h = __half2float(*reinterpret_cast<__half*>(&hv16));
                    acc[rg][0] = fmaf(h, f0, acc[rg][0]);
                    acc[rg][1] = fmaf(h, f1, acc[rg][1]);
                }
            }
        }
#pragma unroll
        for (int rg = 0; rg < 2; ++rg)
#pragma unroll
            for (int o = 0; o < 2; ++o) {
                acc[rg][o] += __shfl_xor_sync(0xffffffffu, acc[rg][o], 1);
                acc[rg][o] += __shfl_xor_sync(0xffffffffu, acc[rg][o], 2);
            }
        if ((lane & 3) == 0) {
            const int s0 = blockIdx.x * SEQ_CTA + wid * 32 + rb * 16 + r0;
            if (s0 < B) {
                out[(size_t)s0 * 2 + 0] = acc[0][0] + bfc_s[0];
                out[(size_t)s0 * 2 + 1] = acc[0][1] + bfc_s[1];
            }
            const int s1 = s0 + 8;
            if (s1 < B) {
                out[(size_t)s1 * 2 + 0] = acc[1][0] + bfc_s[0];
                out[(size_t)s1 * 2 + 1] = acc[1][1] + bfc_s[1];
            }
        }
    }
}

extern "C" void kernel_launch(void* const* d_in, const int* in_sizes, int n_in,
                              void* d_out, int out_size)
{
    const float* x    = (const float*)d_in[0];
    const float* W_ih = (const float*)d_in[1];
    const float* W_hh = (const float*)d_in[2];
    const float* b_ih = (const float*)d_in[3];
    const float* b_hh = (const float*)d_in[4];
    const float* W_fc = (const float*)d_in[5];
    const float* b_fc = (const float*)d_in[6];
    float* out = (float*)d_out;

    const int B = in_sizes[0] / T;                // x has B*T elements
    const int blocks = (B + SEQ_CTA - 1) / SEQ_CTA;

    lstm_hmma<<<blocks, 128>>>(x, W_ih, W_hh, b_ih, b_hh, W_fc, b_fc, out, B);
}

// round 10
// speedup vs baseline: 4.3445x; 1.2058x over previous
#include <cuda_runtime.h>
#include <cuda_fp16.h>
#include <cstdint>

// SeqClassLSTM via mma.sync fp16 (sm_103-portable).
// R10: drop the W_lo compensation MMAs — W_hh quantized to a single fp16.
// Tensor work per step halves (gate chain = 2x k16 + 1x k8). Estimated added
// gate error ~4e-5/step -> final rel_err ~4-6e-4 (budget 1e-3; revert if over).
// Keeps R9 structure: 32 seqs/warp (2 rb-blocks sharing B-fragment LDS),
// tanh.approx.f16x2 activations (c stays fp32), gate order n=gate*32+hid so
// gates i,f,g,o of a (seq,hid) land in ONE thread, h via stmatrix/ldmatrix,
// per-warp double buffer, only __syncwarp per step.

using u32 = uint32_t;

constexpr int T = 128;
constexpr int WARPS = 4;
constexpr int SEQ_CTA = 128;   // 32 per warp

__device__ __forceinline__ u32 sm_addr(const void* p) {
    u32 a;
    asm("{ .reg .u64 t; cvta.to.shared.u64 t, %1; cvt.u32.u64 %0, t; }" : "=r"(a) : "l"(p));
    return a;
}
// pack two f32 -> half2 (u32); LOW half = first arg
__device__ __forceinline__ u32 packh(float lo, float hi) {
    __half2 t = __floats2half2_rn(lo, hi);
    return *reinterpret_cast<u32*>(&t);
}
__device__ __forceinline__ __half2 asH2(u32 v) { return *reinterpret_cast<__half2*>(&v); }
__device__ __forceinline__ u32 asU(__half2 v) { return *reinterpret_cast<u32*>(&v); }
__device__ __forceinline__ __half2 tanh_h2(__half2 v) {
    u32 r, a = asU(v);
    asm("tanh.approx.f16x2 %0, %1;" : "=r"(r) : "r"(a));
    return asH2(r);
}

__device__ __forceinline__ void ldm4(u32 r[4], u32 a) {
    asm volatile("ldmatrix.sync.aligned.m8n8.x4.shared.b16 {%0,%1,%2,%3}, [%4];"
                 : "=r"(r[0]), "=r"(r[1]), "=r"(r[2]), "=r"(r[3]) : "r"(a));
}
__device__ __forceinline__ void ldm2(u32 r[2], u32 a) {
    asm volatile("ldmatrix.sync.aligned.m8n8.x2.shared.b16 {%0,%1}, [%2];"
                 : "=r"(r[0]), "=r"(r[1]) : "r"(a));
}
__device__ __forceinline__ void stm4(u32 a, u32 r0, u32 r1, u32 r2, u32 r3) {
    asm volatile("stmatrix.sync.aligned.m8n8.x4.shared.b16 [%0], {%1,%2,%3,%4};"
                 :: "r"(a), "r"(r0), "r"(r1), "r"(r2), "r"(r3) : "memory");
}
__device__ __forceinline__ void lds128(u32 r[4], u32 a) {
    asm volatile("ld.shared.v4.b32 {%0,%1,%2,%3}, [%4];"
                 : "=r"(r[0]), "=r"(r[1]), "=r"(r[2]), "=r"(r[3]) : "r"(a));
}
__device__ __forceinline__ u32 lds32(u32 a) {
    u32 r;
    asm volatile("ld.shared.u32 %0, [%1];" : "=r"(r) : "r"(a));
    return r;
}
__device__ __forceinline__ void sts128(u32 a, u32 r0, u32 r1, u32 r2, u32 r3) {
    asm volatile("st.shared.v4.b32 [%0], {%1,%2,%3,%4};"
                 :: "r"(a), "r"(r0), "r"(r1), "r"(r2), "r"(r3) : "memory");
}
__device__ __forceinline__ void mma16816(float d[4], const u32 a[4], u32 b0, u32 b1) {
    asm volatile("mma.sync.aligned.m16n8k16.row.col.f32.f16.f16.f32 "
                 "{%0,%1,%2,%3}, {%4,%5,%6,%7}, {%8,%9}, {%0,%1,%2,%3};"
                 : "+f"(d[0]), "+f"(d[1]), "+f"(d[2]), "+f"(d[3])
                 : "r"(a[0]), "r"(a[1]), "r"(a[2]), "r"(a[3]), "r"(b0), "r"(b1));
}
__device__ __forceinline__ void mma1688(float d[4], const u32 a[2], u32 b0) {
    asm volatile("mma.sync.aligned.m16n8k8.row.col.f32.f16.f16.f32 "
                 "{%0,%1,%2,%3}, {%4,%5}, {%6}, {%0,%1,%2,%3};"
                 : "+f"(d[0]), "+f"(d[1]), "+f"(d[2]), "+f"(d[3])
                 : "r"(a[0]), "r"(a[1]), "r"(b0));
}

__global__ void __launch_bounds__(128, 3)
lstm_hmma(const float* __restrict__ x,
          const float* __restrict__ W_ih,
          const float* __restrict__ W_hh,
          const float* __restrict__ b_ih,
          const float* __restrict__ b_hh,
          const float* __restrict__ W_fc,
          const float* __restrict__ b_fc,
          float* __restrict__ out,
          int B)
{
    // Btab[tau*32 + lane][4]: W_hi fragments only. 8KB.
    __shared__ u32 Btab[16 * 32 * 4];
    __shared__ u32 bxs[16 * 32];                       // k8 bias/x B-frags, 2KB
    // Per-warp A buffers: 2 rb-blocks x 1KB, double-buffered. 16KB.
    __shared__ __align__(16) u32 hbuf[WARPS][2][512];
    __shared__ __align__(16) u32 xtile[WARPS][128];    // 32 rows x 16B
    __shared__ float wfc_s[64];
    __shared__ float bfc_s[2];

    const int tid = threadIdx.x;
    const int wid = tid >> 5, lane = tid & 31;

    // ---- weight-fragment table (single fp16 W_hh) ----
    for (int i = tid; i < 16 * 32 * 4; i += 128) {
        const int j   = i & 3;
        const int ln  = (i >> 2) & 31;
        const int tau = i >> 7;
        const int n = tau * 8 + (ln >> 2);
        const int k = ((j >> 1) * 16) + ((j & 1) * 8) + 2 * (ln & 3);
        Btab[i] = packh(W_hh[n * 32 + k], W_hh[n * 32 + k + 1]);
    }
    // ---- k8 (bias/x) B fragments table ----
    for (int i = tid; i < 16 * 32; i += 128) {
        const int ln = i & 31, tau = i >> 5;
        const int sel = ln & 3;
        const int n = tau * 8 + (ln >> 2);
        const float bias = b_ih[n] + b_hh[n];
        const float wx = W_ih[n];
        const float bh = __half2float(__float2half_rn(bias));
        const float wh = __half2float(__float2half_rn(wx));
        u32 v;
        if (sel == 0)      v = packh(bh, bias - bh);      // k0=b_hi, k1=b_lo
        else if (sel == 1) v = packh(wh, wh);             // k2,k3 = wx_hi
        else if (sel == 2) v = packh(wx - wh, 0.0f);      // k4 = wx_lo
        else               v = 0u;
        bxs[i] = v;
    }

    for (int i = tid; i < WARPS * 2 * 512; i += 128) (&hbuf[0][0][0])[i] = 0;
    for (int i = tid; i < WARPS * 128; i += 128) (&xtile[0][0])[i] = 0;
    if (tid < 64) wfc_s[tid] = W_fc[tid];
    if (tid < 2) bfc_s[tid] = b_fc[tid];
    __syncthreads();

    const u32 hb0 = sm_addr(&hbuf[wid][0][0]);
    const u32 hb1 = sm_addr(&hbuf[wid][1][0]);
    const u32 xb  = sm_addr(&xtile[wid][0]);
    const u32 btb = sm_addr(Btab);
    const u32 bxb = sm_addr(bxs);
    const u32 lmo  = ((u32)(lane >> 3) * 128u) + ((u32)(lane & 7) * 16u);
    const u32 lmo2 = ((u32)((lane >> 3) & 1) * 128u) + ((u32)(lane & 7) * 16u);

    // each lane owns x-row = lane (seq within warp)
    const int seqr = blockIdx.x * SEQ_CTA + wid * 32 + lane;
    const bool sv = (seqr < B);

    float xn = sv ? __ldg(&x[(size_t)seqr * T]) : 0.0f;
    {
        const float xh = __half2float(__float2half_rn(xn));
        sts128(xb + (u32)lane * 16u, 0x3C003C00u, packh(xh, xn - xh), packh(xh, 0.0f), 0u);
    }
    __syncwarp();

    float cst[32];
#pragma unroll
    for (int i = 0; i < 32; ++i) cst[i] = 0.0f;

    const __half2 H05 = __floats2half2_rn(0.5f, 0.5f);

#pragma unroll 1
    for (int t = 0; t < T; ++t) {
        const u32 rbuf = (t & 1) ? hb1 : hb0;
        const u32 wbuf = (t & 1) ? hb0 : hb1;
        u32 A0[2][4], A1[2][4], Ax[2][2];
#pragma unroll
        for (int rb = 0; rb < 2; ++rb) {
            ldm4(A0[rb], rbuf + (u32)rb * 1024u + lmo);
            ldm4(A1[rb], rbuf + (u32)rb * 1024u + 512u + lmo);
            ldm2(Ax[rb], xb + (u32)rb * 256u + lmo2);
        }

        float xnext = (sv && (t + 1) < T) ? __ldg(&x[(size_t)seqr * T + t + 1]) : 0.0f;

        u32 hst[2][8];
#pragma unroll
        for (int q = 0; q < 4; ++q) {
            float dd[2][4][4];
#pragma unroll
            for (int gate = 0; gate < 4; ++gate) {
                const int tau = q + gate * 4;
                u32 bh[4];
                lds128(bh, btb + (u32)(tau * 32 + lane) * 16u);
                const u32 bxv = lds32(bxb + (u32)(tau * 32 + lane) * 4u);
#pragma unroll
                for (int rb = 0; rb < 2; ++rb) {
                    float* d = dd[rb][gate];
                    d[0] = 0.0f; d[1] = 0.0f; d[2] = 0.0f; d[3] = 0.0f;
                    mma16816(d, A0[rb], bh[0], bh[1]);
                    mma16816(d, A1[rb], bh[2], bh[3]);
                    mma1688(d, Ax[rb], bxv);
                }
            }
            // f16x2 epilogue: 10 MUFU per (q,rb) covering 4 cells
#pragma unroll
            for (int rb = 0; rb < 2; ++rb) {
#pragma unroll
                for (int pr = 0; pr < 2; ++pr) {
                    const int e = 2 * pr;
                    const __half2 iv = asH2(packh(dd[rb][0][e], dd[rb][0][e + 1]));
                    const __half2 fv = asH2(packh(dd[rb][1][e], dd[rb][1][e + 1]));
                    const __half2 gv = asH2(packh(dd[rb][2][e], dd[rb][2][e + 1]));
                    const __half2 ov = asH2(packh(dd[rb][3][e], dd[rb][3][e + 1]));
                    const __half2 si = __hfma2(tanh_h2(__hmul2(iv, H05)), H05, H05);
                    const __half2 sf = __hfma2(tanh_h2(__hmul2(fv, H05)), H05, H05);
                    const __half2 tg = tanh_h2(gv);
                    const __half2 so = __hfma2(tanh_h2(__hmul2(ov, H05)), H05, H05);
                    const __half2 p = __hmul2(si, tg);
                    const int ci = (rb * 2 + pr) * 8 + q * 2;
                    const float cn0 = fmaf(__low2float(sf),  cst[ci],     __low2float(p));
                    const float cn1 = fmaf(__high2float(sf), cst[ci + 1], __high2float(p));
                    cst[ci] = cn0;
                    cst[ci + 1] = cn1;
                    const __half2 tc = tanh_h2(asH2(packh(cn0, cn1)));
                    hst[rb][q * 2 + pr] = asU(__hmul2(so, tc));
                }
            }
        }
#pragma unroll
        for (int rb = 0; rb < 2; ++rb) {
            stm4(wbuf + (u32)rb * 1024u + lmo,
                 hst[rb][0], hst[rb][1], hst[rb][2], hst[rb][3]);
            stm4(wbuf + (u32)rb * 1024u + 512u + lmo,
                 hst[rb][4], hst[rb][5], hst[rb][6], hst[rb][7]);
        }
        {
            const float xh = __half2float(__float2half_rn(xnext));
            sts128(xb + (u32)lane * 16u, 0x3C003C00u, packh(xh, xnext - xh),
                   packh(xh, 0.0f), 0u);
        }
        __syncwarp();
    }

    // ---- FC from final h (hbuf parity 0; T even) ----
    const int a2 = 2 * (lane & 3);
    const int r0 = lane >> 2;
#pragma unroll
    for (int rb = 0; rb < 2; ++rb) {
        float acc[2][2] = {{0.0f, 0.0f}, {0.0f, 0.0f}};
#pragma unroll
        for (int q = 0; q < 4; ++q) {
#pragma unroll
            for (int e = 0; e < 2; ++e) {
                const int hid = 8 * q + a2 + e;
                const int chunk = hid >> 4;
                const int kk = hid & 15;
                const int khalf = kk >> 3;
                const int col = kk & 7;
                const float f0 = wfc_s[hid];
                const float f1 = wfc_s[32 + hid];
#pragma unroll
                for (int rg = 0; rg < 2; ++rg) {
                    const u32 ahi = hb0 + (u32)rb * 1024u
                                  + (u32)(chunk * 4 + khalf * 2 + rg) * 128u
                                  + (u32)r0 * 16u + (u32)col * 2u;
                    u32 hv16;
                    asm volatile("ld.shared.u16 %0, [%1];" : "=r"(hv16) : "r"(ahi));
                    const float h = __half2float(*reinterpret_cast<__half*>(&hv16));
                    acc[rg][0] = fmaf(h, f0, acc[rg][0]);
                    acc[rg][1] = fmaf(h, f1, acc[rg][1]);
                }
            }
        }
#pragma unroll
        for (int rg = 0; rg < 2; ++rg)
#pragma unroll
            for (int o = 0; o < 2; ++o) {
                acc[rg][o] += __shfl_xor_sync(0xffffffffu, acc[rg][o], 1);
                acc[rg][o] += __shfl_xor_sync(0xffffffffu, acc[rg][o], 2);
            }
        if ((lane & 3) == 0) {
            const int s0 = blockIdx.x * SEQ_CTA + wid * 32 + rb * 16 + r0;
            if (s0 < B) {
                out[(size_t)s0 * 2 + 0] = acc[0][0] + bfc_s[0];
                out[(size_t)s0 * 2 + 1] = acc[0][1] + bfc_s[1];
            }
            const int s1 = s0 + 8;
            if (s1 < B) {
                out[(size_t)s1 * 2 + 0] = acc[1][0] + bfc_s[0];
                out[(size_t)s1 * 2 + 1] = acc[1][1] + bfc_s[1];
            }
        }
    }
}

extern "C" void kernel_launch(void* const* d_in, const int* in_sizes, int n_in,
                              void* d_out, int out_size)
{
    const float* x    = (const float*)d_in[0];
    const float* W_ih = (const float*)d_in[1];
    const float* W_hh = (const float*)d_in[2];
    const float* b_ih = (const float*)d_in[3];
    const float* b_hh = (const float*)d_in[4];
    const float* W_fc = (const float*)d_in[5];
    const float* b_fc = (const float*)d_in[6];
    float* out = (float*)d_out;

    const int B = in_sizes[0] / T;                // x has B*T elements
    const int blocks = (B + SEQ_CTA - 1) / SEQ_CTA;

    lstm_hmma<<<blocks, 128>>>(x, W_ih, W_hh, b_ih, b_hh, W_fc, b_fc, out, B);
}

// round 11
// speedup vs baseline: 4.4157x; 1.0164x over previous
#include <cuda_runtime.h>
#include <cuda_fp16.h>
#include <cstdint>

// SeqClassLSTM via mma.sync fp16 (sm_103-portable).
// R11: (1) occupancy 3->4 CTAs/SM: rb-block processed as OUTER loop so only
// half the A-fragments/accumulators/h-outputs are live at once (regs 153->
// <=128); Btab fragments reloaded per rb (L1 has headroom). (2) i/f/o rows
// of W_hh/bias/W_ih prescaled by 0.5 (exact) so the MMA emits tanh's argument
// v/2 directly — removes 3 hmul2 per epilogue unit.
// Structure from R10: 32 seqs/warp, single-fp16 W_hh, tanh.approx.f16x2
// activations (c stays fp32), gate order n=gate*32+hid (gates of a (seq,hid)
// in one thread), h via stmatrix/ldmatrix, per-warp double buffer, only
// __syncwarp per step.

using u32 = uint32_t;

constexpr int T = 128;
constexpr int WARPS = 4;
constexpr int SEQ_CTA = 128;   // 32 per warp

__device__ __forceinline__ u32 sm_addr(const void* p) {
    u32 a;
    asm("{ .reg .u64 t; cvta.to.shared.u64 t, %1; cvt.u32.u64 %0, t; }" : "=r"(a) : "l"(p));
    return a;
}
// pack two f32 -> half2 (u32); LOW half = first arg
__device__ __forceinline__ u32 packh(float lo, float hi) {
    __half2 t = __floats2half2_rn(lo, hi);
    return *reinterpret_cast<u32*>(&t);
}
__device__ __forceinline__ __half2 asH2(u32 v) { return *reinterpret_cast<__half2*>(&v); }
__device__ __forceinline__ u32 asU(__half2 v) { return *reinterpret_cast<u32*>(&v); }
__device__ __forceinline__ __half2 tanh_h2(__half2 v) {
    u32 r, a = asU(v);
    asm("tanh.approx.f16x2 %0, %1;" : "=r"(r) : "r"(a));
    return asH2(r);
}

__device__ __forceinline__ void ldm4(u32 r[4], u32 a) {
    asm volatile("ldmatrix.sync.aligned.m8n8.x4.shared.b16 {%0,%1,%2,%3}, [%4];"
                 : "=r"(r[0]), "=r"(r[1]), "=r"(r[2]), "=r"(r[3]) : "r"(a));
}
__device__ __forceinline__ void ldm2(u32 r[2], u32 a) {
    asm volatile("ldmatrix.sync.aligned.m8n8.x2.shared.b16 {%0,%1}, [%2];"
                 : "=r"(r[0]), "=r"(r[1]) : "r"(a));
}
__device__ __forceinline__ void stm4(u32 a, u32 r0, u32 r1, u32 r2, u32 r3) {
    asm volatile("stmatrix.sync.aligned.m8n8.x4.shared.b16 [%0], {%1,%2,%3,%4};"
                 :: "r"(a), "r"(r0), "r"(r1), "r"(r2), "r"(r3) : "memory");
}
__device__ __forceinline__ void lds128(u32 r[4], u32 a) {
    asm volatile("ld.shared.v4.b32 {%0,%1,%2,%3}, [%4];"
                 : "=r"(r[0]), "=r"(r[1]), "=r"(r[2]), "=r"(r[3]) : "r"(a));
}
__device__ __forceinline__ u32 lds32(u32 a) {
    u32 r;
    asm volatile("ld.shared.u32 %0, [%1];" : "=r"(r) : "r"(a));
    return r;
}
__device__ __forceinline__ void sts128(u32 a, u32 r0, u32 r1, u32 r2, u32 r3) {
    asm volatile("st.shared.v4.b32 [%0], {%1,%2,%3,%4};"
                 :: "r"(a), "r"(r0), "r"(r1), "r"(r2), "r"(r3) : "memory");
}
__device__ __forceinline__ void mma16816(float d[4], const u32 a[4], u32 b0, u32 b1) {
    asm volatile("mma.sync.aligned.m16n8k16.row.col.f32.f16.f16.f32 "
                 "{%0,%1,%2,%3}, {%4,%5,%6,%7}, {%8,%9}, {%0,%1,%2,%3};"
                 : "+f"(d[0]), "+f"(d[1]), "+f"(d[2]), "+f"(d[3])
                 : "r"(a[0]), "r"(a[1]), "r"(a[2]), "r"(a[3]), "r"(b0), "r"(b1));
}
__device__ __forceinline__ void mma1688(float d[4], const u32 a[2], u32 b0) {
    asm volatile("mma.sync.aligned.m16n8k8.row.col.f32.f16.f16.f32 "
                 "{%0,%1,%2,%3}, {%4,%5}, {%6}, {%0,%1,%2,%3};"
                 : "+f"(d[0]), "+f"(d[1]), "+f"(d[2]), "+f"(d[3])
                 : "r"(a[0]), "r"(a[1]), "r"(b0));
}

__global__ void __launch_bounds__(128, 4)
lstm_hmma(const float* __restrict__ x,
          const float* __restrict__ W_ih,
          const float* __restrict__ W_hh,
          const float* __restrict__ b_ih,
          const float* __restrict__ b_hh,
          const float* __restrict__ W_fc,
          const float* __restrict__ b_fc,
          float* __restrict__ out,
          int B)
{
    // Btab[tau*32 + lane][4]: W fragments (i/f/o rows prescaled by 0.5). 8KB.
    __shared__ u32 Btab[16 * 32 * 4];
    __shared__ u32 bxs[16 * 32];                       // k8 bias/x B-frags, 2KB
    // Per-warp A buffers: 2 rb-blocks x 1KB, double-buffered. 16KB.
    __shared__ __align__(16) u32 hbuf[WARPS][2][512];
    __shared__ __align__(16) u32 xtile[WARPS][128];    // 32 rows x 16B
    __shared__ float wfc_s[64];
    __shared__ float bfc_s[2];

    const int tid = threadIdx.x;
    const int wid = tid >> 5, lane = tid & 31;

    // ---- weight-fragment table; gate g (==2) unscaled, i/f/o scaled 0.5 ----
    for (int i = tid; i < 16 * 32 * 4; i += 128) {
        const int j   = i & 3;
        const int ln  = (i >> 2) & 31;
        const int tau = i >> 7;
        const int gate = tau >> 2;
        const float s = (gate == 2) ? 1.0f : 0.5f;
        const int n = tau * 8 + (ln >> 2);
        const int k = ((j >> 1) * 16) + ((j & 1) * 8) + 2 * (ln & 3);
        Btab[i] = packh(s * W_hh[n * 32 + k], s * W_hh[n * 32 + k + 1]);
    }
    // ---- k8 (bias/x) B fragments table (same 0.5 prescale on i/f/o) ----
    for (int i = tid; i < 16 * 32; i += 128) {
        const int ln = i & 31, tau = i >> 5;
        const int gate = tau >> 2;
        const float s = (gate == 2) ? 1.0f : 0.5f;
        const int sel = ln & 3;
        const int n = tau * 8 + (ln >> 2);
        const float bias = s * (b_ih[n] + b_hh[n]);
        const float wx = s * W_ih[n];
        const float bh = __half2float(__float2half_rn(bias));
        const float wh = __half2float(__float2half_rn(wx));
        u32 v;
        if (sel == 0)      v = packh(bh, bias - bh);      // k0=b_hi, k1=b_lo
        else if (sel == 1) v = packh(wh, wh);             // k2,k3 = wx_hi
        else if (sel == 2) v = packh(wx - wh, 0.0f);      // k4 = wx_lo
        else               v = 0u;
        bxs[i] = v;
    }

    for (int i = tid; i < WARPS * 2 * 512; i += 128) (&hbuf[0][0][0])[i] = 0;
    for (int i = tid; i < WARPS * 128; i += 128) (&xtile[0][0])[i] = 0;
    if (tid < 64) wfc_s[tid] = W_fc[tid];
    if (tid < 2) bfc_s[tid] = b_fc[tid];
    __syncthreads();

    const u32 hb0 = sm_addr(&hbuf[wid][0][0]);
    const u32 hb1 = sm_addr(&hbuf[wid][1][0]);
    const u32 xb  = sm_addr(&xtile[wid][0]);
    const u32 btb = sm_addr(Btab);
    const u32 bxb = sm_addr(bxs);
    const u32 lmo  = ((u32)(lane >> 3) * 128u) + ((u32)(lane & 7) * 16u);
    const u32 lmo2 = ((u32)((lane >> 3) & 1) * 128u) + ((u32)(lane & 7) * 16u);

    // each lane owns x-row = lane (seq within warp)
    const int seqr = blockIdx.x * SEQ_CTA + wid * 32 + lane;
    const bool sv = (seqr < B);

    float xn = sv ? __ldg(&x[(size_t)seqr * T]) : 0.0f;
    {
        const float xh = __half2float(__float2half_rn(xn));
        sts128(xb + (u32)lane * 16u, 0x3C003C00u, packh(xh, xn - xh), packh(xh, 0.0f), 0u);
    }
    __syncwarp();

    float cst[32];
#pragma unroll
    for (int i = 0; i < 32; ++i) cst[i] = 0.0f;

    const __half2 H05 = __floats2half2_rn(0.5f, 0.5f);

#pragma unroll 1
    for (int t = 0; t < T; ++t) {
        const u32 rbuf = (t & 1) ? hb1 : hb0;
        const u32 wbuf = (t & 1) ? hb0 : hb1;

        float xnext = (sv && (t + 1) < T) ? __ldg(&x[(size_t)seqr * T + t + 1]) : 0.0f;

        // rb OUTER: halves live registers (A frags, dd, hst per half)
#pragma unroll
        for (int rb = 0; rb < 2; ++rb) {
            u32 A0[4], A1[4], Ax[2];
            ldm4(A0, rbuf + (u32)rb * 1024u + lmo);
            ldm4(A1, rbuf + (u32)rb * 1024u + 512u + lmo);
            ldm2(Ax, xb + (u32)rb * 256u + lmo2);

            u32 hst[8];
#pragma unroll
            for (int q = 0; q < 4; ++q) {
                float dd[4][4];
#pragma unroll
                for (int gate = 0; gate < 4; ++gate) {
                    const int tau = q + gate * 4;
                    u32 bh[4];
                    lds128(bh, btb + (u32)(tau * 32 + lane) * 16u);
                    const u32 bxv = lds32(bxb + (u32)(tau * 32 + lane) * 4u);
                    float* d = dd[gate];
                    d[0] = 0.0f; d[1] = 0.0f; d[2] = 0.0f; d[3] = 0.0f;
                    mma16816(d, A0, bh[0], bh[1]);
                    mma16816(d, A1, bh[2], bh[3]);
                    mma1688(d, Ax, bxv);
                }
                // epilogue: dd for i/f/o is already v/2 (prescaled weights)
#pragma unroll
                for (int pr = 0; pr < 2; ++pr) {
                    const int e = 2 * pr;
                    const __half2 iv = asH2(packh(dd[0][e], dd[0][e + 1]));
                    const __half2 fv = asH2(packh(dd[1][e], dd[1][e + 1]));
                    const __half2 gv = asH2(packh(dd[2][e], dd[2][e + 1]));
                    const __half2 ov = asH2(packh(dd[3][e], dd[3][e + 1]));
                    const __half2 si = __hfma2(tanh_h2(iv), H05, H05);
                    const __half2 sf = __hfma2(tanh_h2(fv), H05, H05);
                    const __half2 tg = tanh_h2(gv);
                    const __half2 so = __hfma2(tanh_h2(ov), H05, H05);
                    const __half2 p = __hmul2(si, tg);
                    const int ci = (rb * 2 + pr) * 8 + q * 2;
                    const float cn0 = fmaf(__low2float(sf),  cst[ci],     __low2float(p));
                    const float cn1 = fmaf(__high2float(sf), cst[ci + 1], __high2float(p));
                    cst[ci] = cn0;
                    cst[ci + 1] = cn1;
                    const __half2 tc = tanh_h2(asH2(packh(cn0, cn1)));
                    hst[q * 2 + pr] = asU(__hmul2(so, tc));
                }
            }
            stm4(wbuf + (u32)rb * 1024u + lmo,
                 hst[0], hst[1], hst[2], hst[3]);
            stm4(wbuf + (u32)rb * 1024u + 512u + lmo,
                 hst[4], hst[5], hst[6], hst[7]);
        }
        {
            const float xh = __half2float(__float2half_rn(xnext));
            sts128(xb + (u32)lane * 16u, 0x3C003C00u, packh(xh, xnext - xh),
                   packh(xh, 0.0f), 0u);
        }
        __syncwarp();
    }

    // ---- FC from final h (hbuf parity 0; T even) ----
    const int a2 = 2 * (lane & 3);
    const int r0 = lane >> 2;
#pragma unroll
    for (int rb = 0; rb < 2; ++rb) {
        float acc[2][2] = {{0.0f, 0.0f}, {0.0f, 0.0f}};
#pragma unroll
        for (int q = 0; q < 4; ++q) {
#pragma unroll
            for (int e = 0; e < 2; ++e) {
                const int hid = 8 * q + a2 + e;
                const int chunk = hid >> 4;
                const int kk = hid & 15;
                const int khalf = kk >> 3;
                const int col = kk & 7;
                const float f0 = wfc_s[hid];
                const float f1 = wfc_s[32 + hid];
#pragma unroll
                for (int rg = 0; rg < 2; ++rg) {
                    const u32 ahi = hb0 + (u32)rb * 1024u
                                  + (u32)(chunk * 4 + khalf * 2 + rg) * 128u
                                  + (u32)r0 * 16u + (u32)col * 2u;
                    u32 hv16;
                    asm volatile("ld.shared.u16 %0, [%1];" : "=r"(hv16) : "r"(ahi));
                    const float h = __half2float(*reinterpret_cast<__half*>(&hv16));
                    acc[rg][0] = fmaf(h, f0, acc[rg][0]);
                    acc[rg][1] = fmaf(h, f1, acc[rg][1]);
                }
            }
        }
#pragma unroll
        for (int rg = 0; rg < 2; ++rg)
#pragma unroll
            for (int o = 0; o < 2; ++o) {
                acc[rg][o] += __shfl_xor_sync(0xffffffffu, acc[rg][o], 1);
                acc[rg][o] += __shfl_xor_sync(0xffffffffu, acc[rg][o], 2);
            }
        if ((lane & 3) == 0) {
            const int s0 = blockIdx.x * SEQ_CTA + wid * 32 + rb * 16 + r0;
            if (s0 < B) {
                out[(size_t)s0 * 2 + 0] = acc[0][0] + bfc_s[0];
                out[(size_t)s0 * 2 + 1] = acc[0][1] + bfc_s[1];
            }
            const int s1 = s0 + 8;
            if (s1 < B) {
                out[(size_t)s1 * 2 + 0] = acc[1][0] + bfc_s[0];
                out[(size_t)s1 * 2 + 1] = acc[1][1] + bfc_s[1];
            }
        }
    }
}

extern "C" void kernel_launch(void* const* d_in, const int* in_sizes, int n_in,
                              void* d_out, int out_size)
{
    const float* x    = (const float*)d_in[0];
    const float* W_ih = (const float*)d_in[1];
    const float* W_hh = (const float*)d_in[2];
    const float* b_ih = (const float*)d_in[3];
    const float* b_hh = (const float*)d_in[4];
    const float* W_fc = (const float*)d_in[5];
    const float* b_fc = (const float*)d_in[6];
    float* out = (float*)d_out;

    const int B = in_sizes[0] / T;                // x has B*T elements
    const int blocks = (B + SEQ_CTA - 1) / SEQ_CTA;

    lstm_hmma<<<blocks, 128>>>(x, W_ih, W_hh, b_ih, b_hh, W_fc, b_fc, out, B);
}

// round 12
// speedup vs baseline: 4.4161x; 1.0001x over previous
#include <cuda_runtime.h>
#include <cuda_fp16.h>
#include <cstdint>

// SeqClassLSTM via mma.sync fp16 (sm_103-portable).
// R11: (1) occupancy 3->4 CTAs/SM: rb-block processed as OUTER loop so only
// half the A-fragments/accumulators/h-outputs are live at once (regs 153->
// <=128); Btab fragments reloaded per rb (L1 has headroom). (2) i/f/o rows
// of W_hh/bias/W_ih prescaled by 0.5 (exact) so the MMA emits tanh's argument
// v/2 directly — removes 3 hmul2 per epilogue unit.
// Structure from R10: 32 seqs/warp, single-fp16 W_hh, tanh.approx.f16x2
// activations (c stays fp32), gate order n=gate*32+hid (gates of a (seq,hid)
// in one thread), h via stmatrix/ldmatrix, per-warp double buffer, only
// __syncwarp per step.

using u32 = uint32_t;

constexpr int T = 128;
constexpr int WARPS = 4;
constexpr int SEQ_CTA = 128;   // 32 per warp

__device__ __forceinline__ u32 sm_addr(const void* p) {
    u32 a;
    asm("{ .reg .u64 t; cvta.to.shared.u64 t, %1; cvt.u32.u64 %0, t; }" : "=r"(a) : "l"(p));
    return a;
}
// pack two f32 -> half2 (u32); LOW half = first arg
__device__ __forceinline__ u32 packh(float lo, float hi) {
    __half2 t = __floats2half2_rn(lo, hi);
    return *reinterpret_cast<u32*>(&t);
}
__device__ __forceinline__ __half2 asH2(u32 v) { return *reinterpret_cast<__half2*>(&v); }
__device__ __forceinline__ u32 asU(__half2 v) { return *reinterpret_cast<u32*>(&v); }
__device__ __forceinline__ __half2 tanh_h2(__half2 v) {
    u32 r, a = asU(v);
    asm("tanh.approx.f16x2 %0, %1;" : "=r"(r) : "r"(a));
    return asH2(r);
}

__device__ __forceinline__ void ldm4(u32 r[4], u32 a) {
    asm volatile("ldmatrix.sync.aligned.m8n8.x4.shared.b16 {%0,%1,%2,%3}, [%4];"
                 : "=r"(r[0]), "=r"(r[1]), "=r"(r[2]), "=r"(r[3]) : "r"(a));
}
__device__ __forceinline__ void ldm2(u32 r[2], u32 a) {
    asm volatile("ldmatrix.sync.aligned.m8n8.x2.shared.b16 {%0,%1}, [%2];"
                 : "=r"(r[0]), "=r"(r[1]) : "r"(a));
}
__device__ __forceinline__ void stm4(u32 a, u32 r0, u32 r1, u32 r2, u32 r3) {
    asm volatile("stmatrix.sync.aligned.m8n8.x4.shared.b16 [%0], {%1,%2,%3,%4};"
                 :: "r"(a), "r"(r0), "r"(r1), "r"(r2), "r"(r3) : "memory");
}
__device__ __forceinline__ void lds128(u32 r[4], u32 a) {
    asm volatile("ld.shared.v4.b32 {%0,%1,%2,%3}, [%4];"
                 : "=r"(r[0]), "=r"(r[1]), "=r"(r[2]), "=r"(r[3]) : "r"(a));
}
__device__ __forceinline__ u32 lds32(u32 a) {
    u32 r;
    asm volatile("ld.shared.u32 %0, [%1];" : "=r"(r) : "r"(a));
    return r;
}
__device__ __forceinline__ void sts128(u32 a, u32 r0, u32 r1, u32 r2, u32 r3) {
    asm volatile("st.shared.v4.b32 [%0], {%1,%2,%3,%4};"
                 :: "r"(a), "r"(r0), "r"(r1), "r"(r2), "r"(r3) : "memory");
}
__device__ __forceinline__ void mma16816(float d[4], const u32 a[4], u32 b0, u32 b1) {
    asm volatile("mma.sync.aligned.m16n8k16.row.col.f32.f16.f16.f32 "
                 "{%0,%1,%2,%3}, {%4,%5,%6,%7}, {%8,%9}, {%0,%1,%2,%3};"
                 : "+f"(d[0]), "+f"(d[1]), "+f"(d[2]), "+f"(d[3])
                 : "r"(a[0]), "r"(a[1]), "r"(a[2]), "r"(a[3]), "r"(b0), "r"(b1));
}
__device__ __forceinline__ void mma1688(float d[4], const u32 a[2], u32 b0) {
    asm volatile("mma.sync.aligned.m16n8k8.row.col.f32.f16.f16.f32 "
                 "{%0,%1,%2,%3}, {%4,%5}, {%6}, {%0,%1,%2,%3};"
                 : "+f"(d[0]), "+f"(d[1]), "+f"(d[2]), "+f"(d[3])
                 : "r"(a[0]), "r"(a[1]), "r"(b0));
}

__global__ void __launch_bounds__(128, 4)
lstm_hmma(const float* __restrict__ x,
          const float* __restrict__ W_ih,
          const float* __restrict__ W_hh,
          const float* __restrict__ b_ih,
          const float* __restrict__ b_hh,
          const float* __restrict__ W_fc,
          const float* __restrict__ b_fc,
          float* __restrict__ out,
          int B)
{
    // Btab[tau*32 + lane][4]: W fragments (i/f/o rows prescaled by 0.5). 8KB.
    __shared__ u32 Btab[16 * 32 * 4];
    __shared__ u32 bxs[16 * 32];                       // k8 bias/x B-frags, 2KB
    // Per-warp A buffers: 2 rb-blocks x 1KB, double-buffered. 16KB.
    __shared__ __align__(16) u32 hbuf[WARPS][2][512];
    __shared__ __align__(16) u32 xtile[WARPS][128];    // 32 rows x 16B
    __shared__ float wfc_s[64];
    __shared__ float bfc_s[2];

    const int tid = threadIdx.x;
    const int wid = tid >> 5, lane = tid & 31;

    // ---- weight-fragment table; gate g (==2) unscaled, i/f/o scaled 0.5 ----
    for (int i = tid; i < 16 * 32 * 4; i += 128) {
        const int j   = i & 3;
        const int ln  = (i >> 2) & 31;
        const int tau = i >> 7;
        const int gate = tau >> 2;
        const float s = (gate == 2) ? 1.0f : 0.5f;
        const int n = tau * 8 + (ln >> 2);
        const int k = ((j >> 1) * 16) + ((j & 1) * 8) + 2 * (ln & 3);
        Btab[i] = packh(s * W_hh[n * 32 + k], s * W_hh[n * 32 + k + 1]);
    }
    // ---- k8 (bias/x) B fragments table (same 0.5 prescale on i/f/o) ----
    for (int i = tid; i < 16 * 32; i += 128) {
        const int ln = i & 31, tau = i >> 5;
        const int gate = tau >> 2;
        const float s = (gate == 2) ? 1.0f : 0.5f;
        const int sel = ln & 3;
        const int n = tau * 8 + (ln >> 2);
        const float bias = s * (b_ih[n] + b_hh[n]);
        const float wx = s * W_ih[n];
        const float bh = __half2float(__float2half_rn(bias));
        const float wh = __half2float(__float2half_rn(wx));
        u32 v;
        if (sel == 0)      v = packh(bh, bias - bh);      // k0=b_hi, k1=b_lo
        else if (sel == 1) v = packh(wh, wh);             // k2,k3 = wx_hi
        else if (sel == 2) v = packh(wx - wh, 0.0f);      // k4 = wx_lo
        else               v = 0u;
        bxs[i] = v;
    }

    for (int i = tid; i < WARPS * 2 * 512; i += 128) (&hbuf[0][0][0])[i] = 0;
    for (int i = tid; i < WARPS * 128; i += 128) (&xtile[0][0])[i] = 0;
    if (tid < 64) wfc_s[tid] = W_fc[tid];
    if (tid < 2) bfc_s[tid] = b_fc[tid];
    __syncthreads();

    const u32 hb0 = sm_addr(&hbuf[wid][0][0]);
    const u32 hb1 = sm_addr(&hbuf[wid][1][0]);
    const u32 xb  = sm_addr(&xtile[wid][0]);
    const u32 btb = sm_addr(Btab);
    const u32 bxb = sm_addr(bxs);
    const u32 lmo  = ((u32)(lane >> 3) * 128u) + ((u32)(lane & 7) * 16u);
    const u32 lmo2 = ((u32)((lane >> 3) & 1) * 128u) + ((u32)(lane & 7) * 16u);

    // each lane owns x-row = lane (seq within warp)
    const int seqr = blockIdx.x * SEQ_CTA + wid * 32 + lane;
    const bool sv = (seqr < B);

    float xn = sv ? __ldg(&x[(size_t)seqr * T]) : 0.0f;
    {
        const float xh = __half2float(__float2half_rn(xn));
        sts128(xb + (u32)lane * 16u, 0x3C003C00u, packh(xh, xn - xh), packh(xh, 0.0f), 0u);
    }
    __syncwarp();

    float cst[32];
#pragma unroll
    for (int i = 0; i < 32; ++i) cst[i] = 0.0f;

    const __half2 H05 = __floats2half2_rn(0.5f, 0.5f);

#pragma unroll 1
    for (int t = 0; t < T; ++t) {
        const u32 rbuf = (t & 1) ? hb1 : hb0;
        const u32 wbuf = (t & 1) ? hb0 : hb1;

        float xnext = (sv && (t + 1) < T) ? __ldg(&x[(size_t)seqr * T + t + 1]) : 0.0f;

        // rb OUTER: halves live registers (A frags, dd, hst per half)
#pragma unroll
        for (int rb = 0; rb < 2; ++rb) {
            u32 A0[4], A1[4], Ax[2];
            ldm4(A0, rbuf + (u32)rb * 1024u + lmo);
            ldm4(A1, rbuf + (u32)rb * 1024u + 512u + lmo);
            ldm2(Ax, xb + (u32)rb * 256u + lmo2);

            u32 hst[8];
#pragma unroll
            for (int q = 0; q < 4; ++q) {
                float dd[4][4];
#pragma unroll
                for (int gate = 0; gate < 4; ++gate) {
                    const int tau = q + gate * 4;
                    u32 bh[4];
                    lds128(bh, btb + (u32)(tau * 32 + lane) * 16u);
                    const u32 bxv = lds32(bxb + (u32)(tau * 32 + lane) * 4u);
                    float* d = dd[gate];
                    d[0] = 0.0f; d[1] = 0.0f; d[2] = 0.0f; d[3] = 0.0f;
                    mma16816(d, A0, bh[0], bh[1]);
                    mma16816(d, A1, bh[2], bh[3]);
                    mma1688(d, Ax, bxv);
                }
                // epilogue: dd for i/f/o is already v/2 (prescaled weights)
#pragma unroll
                for (int pr = 0; pr < 2; ++pr) {
                    const int e = 2 * pr;
                    const __half2 iv = asH2(packh(dd[0][e], dd[0][e + 1]));
                    const __half2 fv = asH2(packh(dd[1][e], dd[1][e + 1]));
                    const __half2 gv = asH2(packh(dd[2][e], dd[2][e + 1]));
                    const __half2 ov = asH2(packh(dd[3][e], dd[3][e + 1]));
                    const __half2 si = __hfma2(tanh_h2(iv), H05, H05);
                    const __half2 sf = __hfma2(tanh_h2(fv), H05, H05);
                    const __half2 tg = tanh_h2(gv);
                    const __half2 so = __hfma2(tanh_h2(ov), H05, H05);
                    const __half2 p = __hmul2(si, tg);
                    const int ci = (rb * 2 + pr) * 8 + q * 2;
                    const float cn0 = fmaf(__low2float(sf),  cst[ci],     __low2float(p));
                    const float cn1 = fmaf(__high2float(sf), cst[ci + 1], __high2float(p));
                    cst[ci] = cn0;
                    cst[ci + 1] = cn1;
                    const __half2 tc = tanh_h2(asH2(packh(cn0, cn1)));
                    hst[q * 2 + pr] = asU(__hmul2(so, tc));
                }
            }
            stm4(wbuf + (u32)rb * 1024u + lmo,
                 hst[0], hst[1], hst[2], hst[3]);
            stm4(wbuf + (u32)rb * 1024u + 512u + lmo,
                 hst[4], hst[5], hst[6], hst[7]);
        }
        {
            const float xh = __half2float(__float2half_rn(xnext));
            sts128(xb + (u32)lane * 16u, 0x3C003C00u, packh(xh, xnext - xh),
                   packh(xh, 0.0f), 0u);
        }
        __syncwarp();
    }

    // ---- FC from final h (hbuf parity 0; T even) ----
    const int a2 = 2 * (lane & 3);
    const int r0 = lane >> 2;
#pragma unroll
    for (int rb = 0; rb < 2; ++rb) {
        float acc[2][2] = {{0.0f, 0.0f}, {0.0f, 0.0f}};
#pragma unroll
        for (int q = 0; q < 4; ++q) {
#pragma unroll
            for (int e = 0; e < 2; ++e) {
                const int hid = 8 * q + a2 + e;
                const int chunk = hid >> 4;
                const int kk = hid & 15;
                const int khalf = kk >> 3;
                const int col = kk & 7;
                const float f0 = wfc_s[hid];
                const float f1 = wfc_s[32 + hid];
#pragma unroll
                for (int rg = 0; rg < 2; ++rg) {
                    const u32 ahi = hb0 + (u32)rb * 1024u
                                  + (u32)(chunk * 4 + khalf * 2 + rg) * 128u
                                  + (u32)r0 * 16u + (u32)col * 2u;
                    u32 hv16;
                    asm volatile("ld.shared.u16 %0, [%1];" : "=r"(hv16) : "r"(ahi));
                    const float h = __half2float(*reinterpret_cast<__half*>(&hv16));
                    acc[rg][0] = fmaf(h, f0, acc[rg][0]);
                    acc[rg][1] = fmaf(h, f1, acc[rg][1]);
                }
            }
        }
#pragma unroll
        for (int rg = 0; rg < 2; ++rg)
#pragma unroll
            for (int o = 0; o < 2; ++o) {
                acc[rg][o] += __shfl_xor_sync(0xffffffffu, acc[rg][o], 1);
                acc[rg][o] += __shfl_xor_sync(0xffffffffu, acc[rg][o], 2);
            }
        if ((lane & 3) == 0) {
            const int s0 = blockIdx.x * SEQ_CTA + wid * 32 + rb * 16 + r0;
            if (s0 < B) {
                out[(size_t)s0 * 2 + 0] = acc[0][0] + bfc_s[0];
                out[(size_t)s0 * 2 + 1] = acc[0][1] + bfc_s[1];
            }
            const int s1 = s0 + 8;
            if (s1 < B) {
                out[(size_t)s1 * 2 + 0] = acc[1][0] + bfc_s[0];
                out[(size_t)s1 * 2 + 1] = acc[1][1] + bfc_s[1];
            }
        }
    }
}

extern "C" void kernel_launch(void* const* d_in, const int* in_sizes, int n_in,
                              void* d_out, int out_size)
{
    const float* x    = (const float*)d_in[0];
    const float* W_ih = (const float*)d_in[1];
    const float* W_hh = (const float*)d_in[2];
    const float* b_ih = (const float*)d_in[3];
    const float* b_hh = (const float*)d_in[4];
    const float* W_fc = (const float*)d_in[5];
    const float* b_fc = (const float*)d_in[6];
    float* out = (float*)d_out;

    const int B = in_sizes[0] / T;                // x has B*T elements
    const int blocks = (B + SEQ_CTA - 1) / SEQ_CTA;

    lstm_hmma<<<blocks, 128>>>(x, W_ih, W_hh, b_ih, b_hh, W_fc, b_fc, out, B);
}